// round 1
// baseline (speedup 1.0000x reference)
#include <cuda_runtime.h>
#include <cuda_bf16.h>
#include <math.h>

// Problem constants
#define Bc  4
#define Sc  2048
#define Dc  512
#define Hc  8
#define Wc  16
#define DKc 64
// M = Bc*Sc = 8192, K = N = 512 for all projection GEMMs

// Scratch (device globals; allocation in kernel_launch is forbidden)
__device__ float g_Q[Bc * Hc * Sc * DKc];   // [b,h,s,dk]
__device__ float g_K[Bc * Hc * Sc * DKc];
__device__ float g_V[Bc * Hc * Sc * DKc];
__device__ float g_ctx[Bc * Sc * Dc];       // [b*s, d]

// ---------------------------------------------------------------------------
// SGEMM core: 128x128 tile, BK=8, 8x8 per thread, 256 threads.
// C[M,512] = A[M,512] @ W[512,512] + bias. No bounds checks (all dims divide).
// ---------------------------------------------------------------------------
struct GemmAcc {
    float acc[8][8];
};

__device__ __forceinline__ void sgemm_128x128(
    const float* __restrict__ A, const float* __restrict__ Wm,
    int rowBase, int colBase, GemmAcc& r)
{
    const int K = 512, N = 512;
    __shared__ float As[8][128];
    __shared__ float Bs[8][128];

    const int tid = threadIdx.x;
    const int ty = tid >> 4;        // 0..15
    const int tx = tid & 15;        // 0..15

    #pragma unroll
    for (int i = 0; i < 8; i++)
        #pragma unroll
        for (int j = 0; j < 8; j++)
            r.acc[i][j] = 0.0f;

    const int arow = tid >> 1;          // 0..127
    const int acol = (tid & 1) * 4;     // 0 or 4
    const int brow = tid >> 5;          // 0..7
    const int bcol = (tid & 31) * 4;    // 0..124

    const float* Aptr = A + (rowBase + arow) * K + acol;
    const float* Bptr = Wm + brow * N + colBase + bcol;

    for (int k0 = 0; k0 < K; k0 += 8) {
        float4 av = *(const float4*)(Aptr + k0);
        As[acol + 0][arow] = av.x;
        As[acol + 1][arow] = av.y;
        As[acol + 2][arow] = av.z;
        As[acol + 3][arow] = av.w;
        float4 bv = *(const float4*)(Bptr + (size_t)k0 * N);
        *(float4*)&Bs[brow][bcol] = bv;
        __syncthreads();

        #pragma unroll
        for (int kk = 0; kk < 8; kk++) {
            float ra[8], rb[8];
            #pragma unroll
            for (int i = 0; i < 8; i++) ra[i] = As[kk][ty * 8 + i];
            #pragma unroll
            for (int j = 0; j < 8; j++) rb[j] = Bs[kk][tx * 8 + j];
            #pragma unroll
            for (int i = 0; i < 8; i++)
                #pragma unroll
                for (int j = 0; j < 8; j++)
                    r.acc[i][j] = fmaf(ra[i], rb[j], r.acc[i][j]);
        }
        __syncthreads();
    }
}

// ---------------------------------------------------------------------------
// Fused QKV projection. blockIdx.z selects {Q, K, V}. Epilogue scatters to
// [b, h, s, dk] layout for the attention kernel.
// ---------------------------------------------------------------------------
__global__ __launch_bounds__(256) void qkv_gemm_kernel(
    const float* __restrict__ q_in, const float* __restrict__ k_in,
    const float* __restrict__ v_in,
    const float* __restrict__ Wq, const float* __restrict__ Wk,
    const float* __restrict__ Wv,
    const float* __restrict__ bq, const float* __restrict__ bk,
    const float* __restrict__ bv)
{
    const float* A; const float* Wm; const float* bias; float* out;
    if (blockIdx.z == 0)      { A = q_in; Wm = Wq; bias = bq; out = g_Q; }
    else if (blockIdx.z == 1) { A = k_in; Wm = Wk; bias = bk; out = g_K; }
    else                      { A = v_in; Wm = Wv; bias = bv; out = g_V; }

    const int rowBase = blockIdx.y * 128;
    const int colBase = blockIdx.x * 128;

    GemmAcc r;
    sgemm_128x128(A, Wm, rowBase, colBase, r);

    const int ty = threadIdx.x >> 4;
    const int tx = threadIdx.x & 15;

    #pragma unroll
    for (int i = 0; i < 8; i++) {
        const int m = rowBase + ty * 8 + i;
        const int b = m >> 11;          // / Sc
        const int s = m & (Sc - 1);
        #pragma unroll
        for (int j = 0; j < 8; j++) {
            const int n = colBase + tx * 8 + j;
            const int h = n >> 6;       // / DKc
            const int dk = n & (DKc - 1);
            out[(((b * Hc + h) * Sc + s) * DKc) + dk] = r.acc[i][j] + bias[n];
        }
    }
}

// ---------------------------------------------------------------------------
// Output projection: d_out = g_ctx @ Wo + bo (plain row-major epilogue)
// ---------------------------------------------------------------------------
__global__ __launch_bounds__(256) void out_gemm_kernel(
    const float* __restrict__ Wo, const float* __restrict__ bo,
    float* __restrict__ out)
{
    const int rowBase = blockIdx.y * 128;
    const int colBase = blockIdx.x * 128;

    GemmAcc r;
    sgemm_128x128(g_ctx, Wo, rowBase, colBase, r);

    const int ty = threadIdx.x >> 4;
    const int tx = threadIdx.x & 15;

    #pragma unroll
    for (int i = 0; i < 8; i++) {
        const int m = rowBase + ty * 8 + i;
        #pragma unroll
        for (int j = 0; j < 8; j++) {
            const int n = colBase + tx * 8 + j;
            out[(size_t)m * Dc + n] = r.acc[i][j] + bo[n];
        }
    }
}

// ---------------------------------------------------------------------------
// Banded local attention, flash-style online softmax.
// grid = (S/TQ, B*H), block = 256 (8 warps). Each warp handles 8 queries.
// K/V halo tile (TQ + 2W = 96 rows x 64) staged in shared memory.
// ---------------------------------------------------------------------------
#define TQ 64
#define HALO_ROWS (TQ + 2 * Wc)   // 96

__global__ __launch_bounds__(256) void attn_kernel()
{
    __shared__ float sK[HALO_ROWS][DKc];
    __shared__ float sV[HALO_ROWS][DKc];

    const int bh = blockIdx.y;          // b*H + h
    const int b = bh / Hc;
    const int h = bh % Hc;
    const int q0 = blockIdx.x * TQ;
    const int kstart = q0 - Wc;         // may be negative

    const long kvBase = (long)bh * Sc * DKc;

    // Cooperative load of K/V halo tile
    for (int idx = threadIdx.x; idx < HALO_ROWS * DKc; idx += blockDim.x) {
        const int r = idx / DKc;
        const int c = idx % DKc;
        const int j = kstart + r;
        if (j >= 0 && j < Sc) {
            sK[r][c] = g_K[kvBase + (long)j * DKc + c];
            sV[r][c] = g_V[kvBase + (long)j * DKc + c];
        }
    }
    __syncthreads();

    const int warp = threadIdx.x >> 5;
    const int lane = threadIdx.x & 31;

    #pragma unroll
    for (int i = 0; i < 8; i++) {
        const int q = q0 + warp * 8 + i;

        // Load this query's vector (2 floats per lane)
        const float2 qv = *(const float2*)&g_Q[kvBase + (long)q * DKc + 2 * lane];

        float m = -INFINITY;
        float l = 0.0f;
        float acc0 = 0.0f, acc1 = 0.0f;

        const int jlo = max(q - Wc, 0);
        const int jhi = min(q + Wc, Sc - 1);

        for (int j = jlo; j <= jhi; j++) {
            const int r = j - kstart;
            const float2 kv = *(const float2*)&sK[r][2 * lane];
            float p = qv.x * kv.x + qv.y * kv.y;
            // full warp butterfly reduce -> every lane holds the score
            #pragma unroll
            for (int off = 16; off > 0; off >>= 1)
                p += __shfl_xor_sync(0xffffffffu, p, off);
            p *= 0.125f;  // 1/sqrt(DK=64)

            const float nm = fmaxf(m, p);
            const float scale = __expf(m - nm);   // exp(-inf)=0 on first iter
            const float w = __expf(p - nm);
            const float2 vv = *(const float2*)&sV[r][2 * lane];
            acc0 = acc0 * scale + w * vv.x;
            acc1 = acc1 * scale + w * vv.y;
            l = l * scale + w;
            m = nm;
        }

        const float inv = 1.0f / l;
        // ctx layout: [b*S + q, D], column h*DK + dk
        float* dst = &g_ctx[((long)(b * Sc + q)) * Dc + h * DKc + 2 * lane];
        dst[0] = acc0 * inv;
        dst[1] = acc1 * inv;
    }
}

// ---------------------------------------------------------------------------
// Launch
// ---------------------------------------------------------------------------
extern "C" void kernel_launch(void* const* d_in, const int* in_sizes, int n_in,
                              void* d_out, int out_size)
{
    const float* query = (const float*)d_in[0];
    const float* key   = (const float*)d_in[1];
    const float* value = (const float*)d_in[2];
    const float* Wq    = (const float*)d_in[3];
    const float* bq    = (const float*)d_in[4];
    const float* Wk    = (const float*)d_in[5];
    const float* bk    = (const float*)d_in[6];
    const float* Wv    = (const float*)d_in[7];
    const float* bv    = (const float*)d_in[8];
    const float* Wo    = (const float*)d_in[9];
    const float* bo    = (const float*)d_in[10];
    float* out = (float*)d_out;

    // QKV projections: M=8192 rows (64 tiles), N=512 (4 tiles), z = Q/K/V
    dim3 gemmGrid(4, 64, 3);
    qkv_gemm_kernel<<<gemmGrid, 256>>>(query, key, value, Wq, Wk, Wv, bq, bk, bv);

    // Banded attention
    dim3 attnGrid(Sc / TQ, Bc * Hc);
    attn_kernel<<<attnGrid, 256>>>();

    // Output projection
    dim3 outGrid(4, 64, 1);
    out_gemm_kernel<<<outGrid, 256>>>(Wo, bo, out);
}

// round 3
// speedup vs baseline: 1.6730x; 1.6730x over previous
#include <cuda_runtime.h>
#include <cuda_bf16.h>
#include <cstdint>
#include <math.h>

// ---------------------------------------------------------------------------
// Problem constants
// ---------------------------------------------------------------------------
#define Bc  4
#define Sc  2048
#define Dc  512
#define Hc  8
#define Wc  16
#define DKc 64
#define Mtot (Bc * Sc)          // 8192
#define NELEM (Mtot * Dc)       // 4194304

// ---------------------------------------------------------------------------
// Device scratch
// ---------------------------------------------------------------------------
__device__ __nv_bfloat16 g_ah[3][NELEM];      // hi split of query/key/value
__device__ __nv_bfloat16 g_al[3][NELEM];      // lo split
__device__ __nv_bfloat16 g_wth[4][Dc * Dc];   // W^T hi: [n][k]
__device__ __nv_bfloat16 g_wtl[4][Dc * Dc];   // W^T lo
__device__ float g_Q[NELEM];                  // projected, [m, 512]
__device__ float g_K[NELEM];
__device__ float g_V[NELEM];
__device__ __nv_bfloat16 g_ch[NELEM];         // ctx hi split [m, 512]
__device__ __nv_bfloat16 g_cl[NELEM];         // ctx lo split

__device__ __forceinline__ uint32_t smem_to_u32(const void* p) {
    uint32_t a;
    asm("{ .reg .u64 t; cvta.to.shared.u64 t, %1; cvt.u32.u64 %0, t; }"
        : "=r"(a) : "l"(p));
    return a;
}

// ---------------------------------------------------------------------------
// bf16x3 GEMM via mma.sync (HMMA, base ISA — tcgen05 not available: harness
// PTX targets sm_103 without the 'a' feature set).
// C[*,512] = (Ah+Al)[M,512] @ (Wh+Wl)^T + bias, via K'=1536 virtual GEMM:
// segment 0: Ah*Wh, segment 1: Ah*Wl, segment 2: Al*Wh.
// CTA tile 128x128, K-chunk 32, double-buffered cp.async, 8 warps (2x4),
// warp tile 64x32, m16n8k16 bf16 mma with fp32 register accumulators.
// ---------------------------------------------------------------------------
#define KCHUNK 32
#define NCHUNK 48   // 1536 / 32
#define TILE_BYTES (128 * KCHUNK * 2)  // 8192

__device__ __forceinline__ void cp_async16(uint32_t sp, const void* gp) {
    asm volatile("cp.async.cg.shared.global [%0], [%1], 16;" :: "r"(sp), "l"(gp));
}
__device__ __forceinline__ void cp_commit() {
    asm volatile("cp.async.commit_group;");
}

// load a 128x32 bf16 tile (rows rowBase.., k offset kk) into swizzled smem
__device__ __forceinline__ void load_tile(
    uint32_t sbase, const __nv_bfloat16* __restrict__ src, int rowBase, int kk)
{
    const int t = threadIdx.x;
    #pragma unroll
    for (int i = 0; i < 2; i++) {
        const int g = t * 2 + i;             // 0..511 granules of 16B
        const int row = g >> 2;
        const int cg = g & 3;
        const int cgs = cg ^ (row & 3);      // swizzle
        const void* gp = src + (size_t)(rowBase + row) * Dc + kk + cg * 8;
        cp_async16(sbase + row * 64 + cgs * 16, gp);
    }
}

__device__ __forceinline__ void ldsm_x4(uint32_t* r, uint32_t addr) {
    asm volatile("ldmatrix.sync.aligned.m8n8.x4.shared.b16 {%0,%1,%2,%3}, [%4];"
                 : "=r"(r[0]), "=r"(r[1]), "=r"(r[2]), "=r"(r[3]) : "r"(addr));
}
__device__ __forceinline__ void ldsm_x2(uint32_t* r, uint32_t addr) {
    asm volatile("ldmatrix.sync.aligned.m8n8.x2.shared.b16 {%0,%1}, [%2];"
                 : "=r"(r[0]), "=r"(r[1]) : "r"(addr));
}
__device__ __forceinline__ void mma16816(
    float* d, const uint32_t* a, const uint32_t* b)
{
    asm volatile(
        "mma.sync.aligned.m16n8k16.row.col.f32.bf16.bf16.f32 "
        "{%0,%1,%2,%3}, {%4,%5,%6,%7}, {%8,%9}, {%0,%1,%2,%3};"
        : "+f"(d[0]), "+f"(d[1]), "+f"(d[2]), "+f"(d[3])
        : "r"(a[0]), "r"(a[1]), "r"(a[2]), "r"(a[3]), "r"(b[0]), "r"(b[1]));
}

__device__ void gemm_core(
    const __nv_bfloat16* __restrict__ Ah, const __nv_bfloat16* __restrict__ Al,
    const __nv_bfloat16* __restrict__ Wh, const __nv_bfloat16* __restrict__ Wl,
    const float* __restrict__ bias, float* __restrict__ dst,
    int rowBase, int colBase)
{
    __shared__ __align__(16) char smA[2][TILE_BYTES];
    __shared__ __align__(16) char smB[2][TILE_BYTES];

    const int tid = threadIdx.x;
    const int wid = tid >> 5;
    const int lane = tid & 31;
    const int wm = wid >> 2;       // 0..1
    const int wn = wid & 3;        // 0..3

    const uint32_t sA0 = smem_to_u32(smA[0]);
    const uint32_t sA1 = smem_to_u32(smA[1]);
    const uint32_t sB0 = smem_to_u32(smB[0]);
    const uint32_t sB1 = smem_to_u32(smB[1]);

    float acc[4][4][4];
    #pragma unroll
    for (int i = 0; i < 4; i++)
        #pragma unroll
        for (int j = 0; j < 4; j++)
            #pragma unroll
            for (int k = 0; k < 4; k++)
                acc[i][j][k] = 0.0f;

    // Per-lane ldmatrix address components (constant over the k-loop)
    // A frag mi: rows = wm*64 + mi*16 + (lane&7) + ((lane>>3)&1)*8, cg hi bit = lane>>4
    int aRow[4], aR3[4];
    #pragma unroll
    for (int mi = 0; mi < 4; mi++) {
        const int r = wm * 64 + mi * 16 + (lane & 7) + (((lane >> 3) & 1) << 3);
        aRow[mi] = r * 64;
        aR3[mi] = r & 3;
    }
    const int aHi = lane >> 4;   // 0/1 -> k-halves
    // B frag ni: rows = wn*32 + ni*8 + (lane&7); k-half = (lane&15)>>3
    int bRow[4], bR3[4];
    #pragma unroll
    for (int ni = 0; ni < 4; ni++) {
        const int r = wn * 32 + ni * 8 + (lane & 7);
        bRow[ni] = r * 64;
        bR3[ni] = r & 3;
    }
    const int bHi = (lane & 15) >> 3;

    // prologue: issue chunks 0, 1
    #pragma unroll
    for (int c = 0; c < 2; c++) {
        // chunk c: segment 0 (Ah, Wh), kk = c*32
        load_tile(c ? sA1 : sA0, Ah, rowBase, c * KCHUNK);
        load_tile(c ? sB1 : sB0, Wh, colBase, c * KCHUNK);
        cp_commit();
    }

    for (int c = 0; c < NCHUNK; c++) {
        if (c < NCHUNK - 2) asm volatile("cp.async.wait_group 1;");
        else                asm volatile("cp.async.wait_group 0;");
        __syncthreads();

        const uint32_t cA = (c & 1) ? sA1 : sA0;
        const uint32_t cB = (c & 1) ? sB1 : sB0;

        #pragma unroll
        for (int ks = 0; ks < 2; ks++) {
            uint32_t af[4][4], bf[4][2];
            #pragma unroll
            for (int mi = 0; mi < 4; mi++) {
                const int cg = (ks * 2 + aHi) ^ aR3[mi];
                ldsm_x4(af[mi], cA + aRow[mi] + cg * 16);
            }
            #pragma unroll
            for (int ni = 0; ni < 4; ni++) {
                const int cg = (ks * 2 + bHi) ^ bR3[ni];
                ldsm_x2(bf[ni], cB + bRow[ni] + cg * 16);
            }
            #pragma unroll
            for (int mi = 0; mi < 4; mi++)
                #pragma unroll
                for (int ni = 0; ni < 4; ni++)
                    mma16816(acc[mi][ni], af[mi], bf[ni]);
        }
        __syncthreads();

        if (c + 2 < NCHUNK) {
            const int cc = c + 2;
            const int seg = cc >> 4;               // 0,1,2
            const int kk = (cc & 15) * KCHUNK;
            const __nv_bfloat16* As = (seg == 2) ? Al : Ah;
            const __nv_bfloat16* Ws = (seg == 1) ? Wl : Wh;
            load_tile((c & 1) ? sA1 : sA0, As, rowBase, kk);
            load_tile((c & 1) ? sB1 : sB0, Ws, colBase, kk);
            cp_commit();
        }
    }

    // epilogue: acc -> dst (+bias)
    const int lr = lane >> 2;       // 0..7
    const int lc = (lane & 3) * 2;
    #pragma unroll
    for (int ni = 0; ni < 4; ni++) {
        const int col = colBase + wn * 32 + ni * 8 + lc;
        const float2 bb = *(const float2*)&bias[col];
        #pragma unroll
        for (int mi = 0; mi < 4; mi++) {
            const int row = rowBase + wm * 64 + mi * 16 + lr;
            float2 v0 = { acc[mi][ni][0] + bb.x, acc[mi][ni][1] + bb.y };
            float2 v1 = { acc[mi][ni][2] + bb.x, acc[mi][ni][3] + bb.y };
            *(float2*)&dst[(size_t)row * Dc + col] = v0;
            *(float2*)&dst[(size_t)(row + 8) * Dc + col] = v1;
        }
    }
}

__global__ __launch_bounds__(256, 2) void qkv_gemm_tc(
    const float* __restrict__ bq, const float* __restrict__ bk,
    const float* __restrict__ bv)
{
    const int z = blockIdx.z;
    const float* bias = (z == 0) ? bq : (z == 1) ? bk : bv;
    float* dst = (z == 0) ? g_Q : (z == 1) ? g_K : g_V;
    gemm_core(g_ah[z], g_al[z], g_wth[z], g_wtl[z], bias, dst,
              blockIdx.y * 128, blockIdx.x * 128);
}

__global__ __launch_bounds__(256, 2) void out_gemm_tc(
    const float* __restrict__ bo, float* __restrict__ out)
{
    gemm_core(g_ch, g_cl, g_wth[3], g_wtl[3], bo, out,
              blockIdx.y * 128, blockIdx.x * 128);
}

// ---------------------------------------------------------------------------
// fp32 -> bf16 hi/lo splits
// ---------------------------------------------------------------------------
__global__ __launch_bounds__(256) void split_inputs_kernel(
    const float* __restrict__ q, const float* __restrict__ k,
    const float* __restrict__ v)
{
    const int z = blockIdx.y;
    const float* src = (z == 0) ? q : (z == 1) ? k : v;
    const size_t i4 = (size_t)blockIdx.x * 256 + threadIdx.x;
    float4 f = ((const float4*)src)[i4];
    float a[4] = {f.x, f.y, f.z, f.w};
    __align__(8) __nv_bfloat16 h[4], lo[4];
    #pragma unroll
    for (int i = 0; i < 4; i++) {
        h[i] = __float2bfloat16_rn(a[i]);
        lo[i] = __float2bfloat16_rn(a[i] - __bfloat162float(h[i]));
    }
    *(uint2*)&g_ah[z][i4 * 4] = *(uint2*)h;
    *(uint2*)&g_al[z][i4 * 4] = *(uint2*)lo;
}

// tiled transpose + split: g_wt*[z][n][k] = split(w[k][n])
__global__ __launch_bounds__(1024) void split_weights_kernel(
    const float* __restrict__ Wq, const float* __restrict__ Wk,
    const float* __restrict__ Wv, const float* __restrict__ Wo)
{
    const int z = blockIdx.z;
    const float* w = (z == 0) ? Wq : (z == 1) ? Wk : (z == 2) ? Wv : Wo;
    __shared__ float s[32][33];
    const int tx = threadIdx.x & 31;
    const int ty = threadIdx.x >> 5;
    const int rb = blockIdx.y * 32;   // k block
    const int cb = blockIdx.x * 32;   // n block
    s[ty][tx] = w[(size_t)(rb + ty) * Dc + cb + tx];
    __syncthreads();
    const float a = s[tx][ty];        // = w[rb+tx][cb+ty]
    const __nv_bfloat16 h = __float2bfloat16_rn(a);
    const __nv_bfloat16 l = __float2bfloat16_rn(a - __bfloat162float(h));
    const size_t o = (size_t)(cb + ty) * Dc + rb + tx;   // [n][k]
    g_wth[z][o] = h;
    g_wtl[z][o] = l;
}

// ---------------------------------------------------------------------------
// Banded local attention (fp32, flash-style). Static 48KB smem.
// Block = 256 thr = 8 warps; each warp: 4 queries x 8-lane dim-groups.
// Writes ctx directly as bf16 hi/lo for the output projection.
// ---------------------------------------------------------------------------
#define TQ 64
#define HALO (TQ + 2 * Wc)    // 96
#define SKW 64

__global__ __launch_bounds__(256) void attn_kernel()
{
    __shared__ float sK[HALO * SKW];
    __shared__ float sV[HALO * SKW];

    const int bh = blockIdx.y;
    const int b = bh >> 3;
    const int h = bh & 7;
    const int q0 = blockIdx.x * TQ;
    const int kstart = q0 - Wc;
    const size_t rowBase = ((size_t)b * Sc) * Dc + h * DKc;

    for (int idx = threadIdx.x; idx < HALO * 16; idx += 256) {
        const int r = idx >> 4;
        const int c4 = idx & 15;
        const int j = kstart + r;
        float4 kv = {0, 0, 0, 0}, vv = {0, 0, 0, 0};
        if (j >= 0 && j < Sc) {
            const size_t off = rowBase + (size_t)j * Dc + c4 * 4;
            kv = *(const float4*)(g_K + off);
            vv = *(const float4*)(g_V + off);
        }
        *(float4*)(sK + r * SKW + c4 * 4) = kv;
        *(float4*)(sV + r * SKW + c4 * 4) = vv;
    }
    __syncthreads();

    const int warp = threadIdx.x >> 5;
    const int lane = threadIdx.x & 31;
    const int lq = lane >> 3;     // local query 0..3
    const int g = lane & 7;       // dim group 0..7

    #pragma unroll
    for (int it = 0; it < 2; it++) {
        const int q = q0 + warp * 8 + it * 4 + lq;
        const size_t qoff = rowBase + (size_t)q * Dc + g * 8;
        const float4 qa = *(const float4*)(g_Q + qoff);
        const float4 qb = *(const float4*)(g_Q + qoff + 4);

        float m = -1e30f, l = 0.0f;
        float4 a0 = {0, 0, 0, 0}, a1 = {0, 0, 0, 0};

        for (int s = 0; s <= 2 * Wc; s++) {
            const int j = q - Wc + s;
            const bool valid = (j >= 0) && (j < Sc);
            const int r = j - kstart;
            const float* kr = sK + r * SKW + g * 8;
            const float4 ka = *(const float4*)kr;
            const float4 kb = *(const float4*)(kr + 4);
            float p = qa.x * ka.x + qa.y * ka.y + qa.z * ka.z + qa.w * ka.w
                    + qb.x * kb.x + qb.y * kb.y + qb.z * kb.z + qb.w * kb.w;
            p += __shfl_xor_sync(0xffffffffu, p, 1);
            p += __shfl_xor_sync(0xffffffffu, p, 2);
            p += __shfl_xor_sync(0xffffffffu, p, 4);
            p *= 0.125f;

            const float pe = valid ? p : -1e30f;
            const float nm = fmaxf(m, pe);
            const float sc = __expf(m - nm);
            const float w = valid ? __expf(p - nm) : 0.0f;

            const float* vr = sV + r * SKW + g * 8;
            const float4 va = *(const float4*)vr;
            const float4 vb = *(const float4*)(vr + 4);
            a0.x = a0.x * sc + w * va.x;
            a0.y = a0.y * sc + w * va.y;
            a0.z = a0.z * sc + w * va.z;
            a0.w = a0.w * sc + w * va.w;
            a1.x = a1.x * sc + w * vb.x;
            a1.y = a1.y * sc + w * vb.y;
            a1.z = a1.z * sc + w * vb.z;
            a1.w = a1.w * sc + w * vb.w;
            l = l * sc + w;
            m = nm;
        }

        const float inv = 1.0f / l;
        float v[8] = {a0.x * inv, a0.y * inv, a0.z * inv, a0.w * inv,
                      a1.x * inv, a1.y * inv, a1.z * inv, a1.w * inv};
        __align__(16) __nv_bfloat16 hi[8], lo[8];
        #pragma unroll
        for (int d = 0; d < 8; d++) {
            hi[d] = __float2bfloat16_rn(v[d]);
            lo[d] = __float2bfloat16_rn(v[d] - __bfloat162float(hi[d]));
        }
        const size_t coff = ((size_t)(b * Sc + q)) * Dc + h * DKc + g * 8;
        *(uint4*)(g_ch + coff) = *(uint4*)hi;
        *(uint4*)(g_cl + coff) = *(uint4*)lo;
    }
}

// ---------------------------------------------------------------------------
// Launch
// ---------------------------------------------------------------------------
extern "C" void kernel_launch(void* const* d_in, const int* in_sizes, int n_in,
                              void* d_out, int out_size)
{
    const float* query = (const float*)d_in[0];
    const float* key   = (const float*)d_in[1];
    const float* value = (const float*)d_in[2];
    const float* bq    = (const float*)d_in[4];
    const float* bk    = (const float*)d_in[6];
    const float* bv    = (const float*)d_in[8];
    const float* Wq    = (const float*)d_in[3];
    const float* Wk    = (const float*)d_in[5];
    const float* Wv    = (const float*)d_in[7];
    const float* Wo    = (const float*)d_in[9];
    const float* bo    = (const float*)d_in[10];
    float* out = (float*)d_out;

    // 1. fp32 -> bf16 hi/lo splits
    split_inputs_kernel<<<dim3(NELEM / 4 / 256, 3), 256>>>(query, key, value);
    split_weights_kernel<<<dim3(16, 16, 4), 1024>>>(Wq, Wk, Wv, Wo);

    // 2. QKV projections (HMMA bf16x3)
    qkv_gemm_tc<<<dim3(4, 64, 3), 256>>>(bq, bk, bv);

    // 3. banded attention
    attn_kernel<<<dim3(Sc / TQ, Bc * Hc), 256>>>();

    // 4. output projection
    out_gemm_tc<<<dim3(4, 64), 256>>>(bo, out);
}